// round 10
// baseline (speedup 1.0000x reference)
#include <cuda_runtime.h>
#include <cuda_bf16.h>

// preds:   (16, 19, 512, 512) float32 = 79,691,776 elems
// targets: (16, 1024, 1024) labels in [0,19) (delivered as int32)
// grid 16 -> 32x32 cells/batch, 16x16 px each.
//
// k_presence: one warp per 2 cells, 8 independent int4 loads (MLP=8).
// k_loss: DUAL-STREAM 19-iter grid-stride: each thread handles float4s at
//         f and f + N4/2 (offset = 152 planes = 8 batches x 19 classes ->
//         same class, batch+8, same cell -> mask = mp[8192], same shift).
//         2 back-to-back LDG.128/iter (x2 with unroll) doubles per-thread MLP.
//         Math: 1 MUFU (ex2) + deg-5 ln(1+t) poly, constant hoisted to N*B0;
//         relu(se?-x:x) = 0.5*(|x| + s*x), s=+-1/float4.
//         Final reduction fused via last-block ticket.

#define N_ELEMS   79691776
#define N4        (N_ELEMS / 4)
#define HALF4     (N4 / 2)              // 9,961,472 float4s = 152 planes
#define NBLK      2048
#define NTHR      256
#define LOSS_STRIDE (NBLK * NTHR)       // 524288 float4s = 8 planes
#define LOSS_ITERS  19                  // 19*8 = 152 planes = half the tensor

// deg-5 poly for ln(1+t), t in [0,1]: B0 + t*(B1 + t*(...)), |err|<=~1e-5
#define B0_D 9.8e-6
#define B1_F 0.9992366f
#define B2_F (-0.4902340f)
#define B3_F 0.2852784f
#define B4_F (-0.1315872f)
#define B5_F 0.0304512f

__device__ unsigned g_masks[16384];
__device__ double   g_partial[NBLK];
__device__ unsigned g_fin = 0;

__device__ __forceinline__ float ex2_(float x) { float r; asm("ex2.approx.f32 %0, %1;" : "=f"(r) : "f"(x)); return r; }

// ---------------------------------------------------------------------------
// Kernel 1: per-cell class-presence bitmask (stride-2 NN downsample).
// ---------------------------------------------------------------------------
__global__ void __launch_bounds__(256) k_presence(const int4* __restrict__ t4) {
    int gwarp = (blockIdx.x * blockDim.x + threadIdx.x) >> 5;  // 0..8191
    int lane  = threadIdx.x & 31;
    int cellA = gwarp << 1;
    int bA    = cellA >> 10;
    int restA = cellA & 1023;
    int chA   = restA >> 5;
    int cwA   = restA & 31;

    int baseA = (bA << 18) + (chA << 13) + (cwA << 3);
    int baseB = baseA + 8;

    int4 qa[4], qb[4];
#pragma unroll
    for (int k = 0; k < 4; ++k) {
        int e = lane + (k << 5);
        int i = e >> 3, jj = e & 7;
        int roff = (i << 9) + jj;
        qa[k] = __ldg(&t4[baseA + roff]);
        qb[k] = __ldg(&t4[baseB + roff]);
    }
    unsigned mA = 0, mB = 0;
#pragma unroll
    for (int k = 0; k < 4; ++k) {
        mA |= (1u << (qa[k].x & 31)) | (1u << (qa[k].z & 31));
        mB |= (1u << (qb[k].x & 31)) | (1u << (qb[k].z & 31));
    }
    mA = __reduce_or_sync(0xFFFFFFFFu, mA);
    mB = __reduce_or_sync(0xFFFFFFFFu, mB);
    if (lane == 0) { g_masks[cellA] = mA; g_masks[cellA + 1] = mB; }
}

// per-element: al += t*q(t)  (= ln(1+e^{-|x|}) - B0),  A += |x|
__device__ __forceinline__ void term(float x, float& al, float& A) {
    float t = ex2_(fabsf(x) * -1.4426950408889634f);
    float q = fmaf(B5_F, t, B4_F);
    q = fmaf(q, t, B3_F);
    q = fmaf(q, t, B2_F);
    q = fmaf(q, t, B1_F);
    al = fmaf(q, t, al);
    A += fabsf(x);
}

// ---------------------------------------------------------------------------
// Kernel 2: dual-stream loss + fused final reduction.
// ---------------------------------------------------------------------------
__global__ void __launch_bounds__(NTHR) k_loss(const float4* __restrict__ p4,
                                               float* __restrict__ out) {
    const int tid  = threadIdx.x;
    const int gtid = blockIdx.x * NTHR + tid;

    // loop-invariant geometry
    int lin    = gtid << 2;
    int w      = lin & 511;
    int h      = (lin >> 9) & 511;
    int cellhw = ((h >> 4) << 5) + (w >> 4);
    int c      = gtid >> 16;               // class at iter 0 (b = 0)
    const unsigned* mp = g_masks + cellhw;
    const float4* pa = p4 + gtid;
    const float4* pb = pa + HALF4;         // +152 planes: same c, batch+8

    float al0 = 0.f, al1 = 0.f, A0 = 0.f, A1 = 0.f, S0 = 0.f, S1 = 0.f;
#pragma unroll 2
    for (int k = 0; k < LOSS_ITERS; ++k) {
        // both loads issued back-to-back (independent)
        float4 va = __ldcs(pa + k * LOSS_STRIDE);
        float4 vb = __ldcs(pb + k * LOSS_STRIDE);
        unsigned m1 = mp[0], m2 = mp[8192];
        float s1 = __int_as_float(0x3F800000u | (((m1 >> c) & 1u) << 31));
        float s2 = __int_as_float(0x3F800000u | (((m2 >> c) & 1u) << 31));
        term(va.x, al0, A0); term(va.y, al1, A1);
        term(va.z, al0, A0); term(va.w, al1, A1);
        term(vb.x, al0, A0); term(vb.y, al1, A1);
        term(vb.z, al0, A0); term(vb.w, al1, A1);
        float da = (va.x + va.y) + (va.z + va.w);
        float db = (vb.x + vb.y) + (vb.z + vb.w);
        S0 = fmaf(s1, da, S0);
        S1 = fmaf(s2, db, S1);
        c += 8; if (c >= 19) { c -= 19; mp += 1024; }
    }

    double acc = (double)(al0 + al1)
               + 0.5 * ((double)(A0 + A1) + (double)(S0 + S1));

    // deterministic block reduction -> g_partial
    __shared__ double smem[NTHR / 32];
    __shared__ int s_last;
    for (int o = 16; o > 0; o >>= 1) acc += __shfl_down_sync(0xFFFFFFFFu, acc, o);
    if ((tid & 31) == 0) smem[tid >> 5] = acc;
    __syncthreads();
    if (tid < (NTHR / 32)) {
        double a = smem[tid];
        for (int o = (NTHR / 64); o > 0; o >>= 1) a += __shfl_down_sync(0xFFu, a, o);
        if (tid == 0) g_partial[blockIdx.x] = a;
    }

    // last block: final deterministic reduction + write + counter reset
    if (tid == 0) {
        __threadfence();
        unsigned old = atomicAdd(&g_fin, 1u);
        s_last = (old == NBLK - 1);
    }
    __syncthreads();
    if (s_last) {
        __threadfence();
        __shared__ double smem2[NTHR / 32];
        double a = 0.0;
        for (int i = tid; i < NBLK; i += NTHR) a += g_partial[i];
        for (int o = 16; o > 0; o >>= 1) a += __shfl_down_sync(0xFFFFFFFFu, a, o);
        if ((tid & 31) == 0) smem2[tid >> 5] = a;
        __syncthreads();
        if (tid < (NTHR / 32)) {
            double v = smem2[tid];
            for (int o = (NTHR / 64); o > 0; o >>= 1) v += __shfl_down_sync(0xFFu, v, o);
            if (tid == 0) {
                double total = v + (double)N_ELEMS * B0_D;
                out[0] = (float)(total * (1.0 / (double)N_ELEMS));
                g_fin = 0;   // reset for next run / graph replay
            }
        }
    }
}

extern "C" void kernel_launch(void* const* d_in, const int* in_sizes, int n_in,
                              void* d_out, int out_size) {
    const float4* preds   = (const float4*)d_in[0];
    const int4*   targets = (const int4*)d_in[1];
    float*        out     = (float*)d_out;
    k_presence<<<1024, 256>>>(targets);
    k_loss<<<NBLK, NTHR>>>(preds, out);
}

// round 11
// speedup vs baseline: 1.0107x; 1.0107x over previous
#include <cuda_runtime.h>
#include <cuda_bf16.h>

// preds:   (16, 19, 512, 512) float32 = 79,691,776 elems
// targets: (16, 1024, 1024) labels in [0,19) (delivered as int32)
// grid 16 -> 32x32 cells/batch, 16x16 px each.
//
// k_presence: one warp per 2 cells, 8 independent int4 loads (MLP=8).
// k_loss: dual-stream 19-iter grid-stride (streams at f and f+N4/2: same
//         class, batch+8, same cell -> second mask is mp[8192], same shift).
//         Math = R4's measured-fastest form: 2 MUFU (ex2+lg2) + 3 fma-pipe
//         + XOR/FMNMX per element; MUFU rides its own pipe under the DRAM
//         stream. In-loop L1-hit mask loads, pointer-bump class wrap.
//         Final reduction fused via last-block ticket.

#define N_ELEMS   79691776
#define N4        (N_ELEMS / 4)
#define HALF4     (N4 / 2)              // 152 planes
#define NBLK      2048
#define NTHR      256
#define LOSS_STRIDE (NBLK * NTHR)       // 524288 float4s = 8 planes
#define LOSS_ITERS  19                  // covers 152 planes per stream

__device__ unsigned g_masks[16384];
__device__ double   g_partial[NBLK];
__device__ unsigned g_fin = 0;

__device__ __forceinline__ float ex2_(float x) { float r; asm("ex2.approx.f32 %0, %1;" : "=f"(r) : "f"(x)); return r; }
__device__ __forceinline__ float lg2_(float x) { float r; asm("lg2.approx.f32 %0, %1;" : "=f"(r) : "f"(x)); return r; }

// ---------------------------------------------------------------------------
// Kernel 1: per-cell class-presence bitmask (stride-2 NN downsample).
// ---------------------------------------------------------------------------
__global__ void __launch_bounds__(256) k_presence(const int4* __restrict__ t4) {
    int gwarp = (blockIdx.x * blockDim.x + threadIdx.x) >> 5;  // 0..8191
    int lane  = threadIdx.x & 31;
    int cellA = gwarp << 1;
    int bA    = cellA >> 10;
    int restA = cellA & 1023;
    int chA   = restA >> 5;
    int cwA   = restA & 31;

    int baseA = (bA << 18) + (chA << 13) + (cwA << 3);
    int baseB = baseA + 8;

    int4 qa[4], qb[4];
#pragma unroll
    for (int k = 0; k < 4; ++k) {
        int e = lane + (k << 5);
        int i = e >> 3, jj = e & 7;
        int roff = (i << 9) + jj;
        qa[k] = __ldg(&t4[baseA + roff]);
        qb[k] = __ldg(&t4[baseB + roff]);
    }
    unsigned mA = 0, mB = 0;
#pragma unroll
    for (int k = 0; k < 4; ++k) {
        mA |= (1u << (qa[k].x & 31)) | (1u << (qa[k].z & 31));
        mB |= (1u << (qb[k].x & 31)) | (1u << (qb[k].z & 31));
    }
    mA = __reduce_or_sync(0xFFFFFFFFu, mA);
    mB = __reduce_or_sync(0xFFFFFFFFu, mB);
    if (lane == 0) { g_masks[cellA] = mA; g_masks[cellA + 1] = mB; }
}

// R4 per-element form: al += lg2(1+e^{-|x|});  aa += relu(se ? -x : x)
__device__ __forceinline__ void bce(float x, unsigned sgn, float& al, float& aa) {
    al += lg2_(1.0f + ex2_(fabsf(x) * -1.4426950408889634f));
    aa += fmaxf(__int_as_float(__float_as_int(x) ^ sgn), 0.0f);
}

// ---------------------------------------------------------------------------
// Kernel 2: dual-stream loss + fused final reduction.
// ---------------------------------------------------------------------------
__global__ void __launch_bounds__(NTHR) k_loss(const float4* __restrict__ p4,
                                               float* __restrict__ out) {
    const int tid  = threadIdx.x;
    const int gtid = blockIdx.x * NTHR + tid;

    // loop-invariant geometry (stride covers exactly 8 (b,c)-planes)
    int lin    = gtid << 2;
    int w      = lin & 511;
    int h      = (lin >> 9) & 511;
    int cellhw = ((h >> 4) << 5) + (w >> 4);
    int c      = gtid >> 16;               // class at iter 0 (b = 0)
    const unsigned* mp = g_masks + cellhw;
    const float4* pa = p4 + gtid;
    const float4* pb = pa + HALF4;         // +152 planes: same c, batch+8

    float al0 = 0.f, al1 = 0.f, aa0 = 0.f, aa1 = 0.f;
#pragma unroll 2
    for (int k = 0; k < LOSS_ITERS; ++k) {
        float4 va = __ldcs(pa + k * LOSS_STRIDE);
        float4 vb = __ldcs(pb + k * LOSS_STRIDE);
        unsigned sgnA = ((mp[0]    >> c) & 1u) << 31;
        unsigned sgnB = ((mp[8192] >> c) & 1u) << 31;
        bce(va.x, sgnA, al0, aa0); bce(va.y, sgnA, al1, aa1);
        bce(va.z, sgnA, al0, aa0); bce(va.w, sgnA, al1, aa1);
        bce(vb.x, sgnB, al0, aa0); bce(vb.y, sgnB, al1, aa1);
        bce(vb.z, sgnB, al0, aa0); bce(vb.w, sgnB, al1, aa1);
        c += 8; if (c >= 19) { c -= 19; mp += 1024; }
    }

    double acc = (double)(al0 + al1) * 0.6931471805599453 + (double)(aa0 + aa1);

    // deterministic block reduction -> g_partial
    __shared__ double smem[NTHR / 32];
    __shared__ int s_last;
    for (int o = 16; o > 0; o >>= 1) acc += __shfl_down_sync(0xFFFFFFFFu, acc, o);
    if ((tid & 31) == 0) smem[tid >> 5] = acc;
    __syncthreads();
    if (tid < (NTHR / 32)) {
        double a = smem[tid];
        for (int o = (NTHR / 64); o > 0; o >>= 1) a += __shfl_down_sync(0xFFu, a, o);
        if (tid == 0) g_partial[blockIdx.x] = a;
    }

    // last block: final deterministic reduction + write + counter reset
    if (tid == 0) {
        __threadfence();
        unsigned old = atomicAdd(&g_fin, 1u);
        s_last = (old == NBLK - 1);
    }
    __syncthreads();
    if (s_last) {
        __threadfence();
        __shared__ double smem2[NTHR / 32];
        double a = 0.0;
        for (int i = tid; i < NBLK; i += NTHR) a += g_partial[i];
        for (int o = 16; o > 0; o >>= 1) a += __shfl_down_sync(0xFFFFFFFFu, a, o);
        if ((tid & 31) == 0) smem2[tid >> 5] = a;
        __syncthreads();
        if (tid < (NTHR / 32)) {
            double v = smem2[tid];
            for (int o = (NTHR / 64); o > 0; o >>= 1) v += __shfl_down_sync(0xFFu, v, o);
            if (tid == 0) {
                out[0] = (float)(v * (1.0 / (double)N_ELEMS));
                g_fin = 0;   // reset for next run / graph replay
            }
        }
    }
}

extern "C" void kernel_launch(void* const* d_in, const int* in_sizes, int n_in,
                              void* d_out, int out_size) {
    const float4* preds   = (const float4*)d_in[0];
    const int4*   targets = (const int4*)d_in[1];
    float*        out     = (float*)d_out;
    k_presence<<<1024, 256>>>(targets);
    k_loss<<<NBLK, NTHR>>>(preds, out);
}

// round 12
// speedup vs baseline: 1.0309x; 1.0199x over previous
#include <cuda_runtime.h>
#include <cuda_bf16.h>

// preds:   (16, 19, 512, 512) float32  = 79,691,776 elems
// targets: (16, 1024, 1024)   labels in [0,19) (delivered as int32)
// grid_size = 16 -> 32x32 cells per batch, 16x16 px each
//
// Strict recombination of best-measured components:
//   k_presence: R10/R11 fast version (one warp per 2 cells, MLP=8)
//   k_loss:     R4 verbatim (single-stream 38 iters, lg2/ex2 math,
//               div-based class indexing, float split accumulators)
//   k_final:    R4 verbatim separate reduction kernel

#define N_ELEMS   79691776
#define N4        (N_ELEMS / 4)          // 19,922,944 float4s
#define N_CELLS   16384
#define LOSS_BLOCKS  2048
#define LOSS_THREADS 256
#define LOSS_STRIDE  (LOSS_BLOCKS * LOSS_THREADS)   // N4/STRIDE = 38 exactly
#define LOSS_ITERS   38

__device__ unsigned g_masks[N_CELLS];
__device__ double   g_partial[LOSS_BLOCKS];

__device__ __forceinline__ float ex2_(float x) { float r; asm("ex2.approx.f32 %0, %1;" : "=f"(r) : "f"(x)); return r; }
__device__ __forceinline__ float lg2_(float x) { float r; asm("lg2.approx.f32 %0, %1;" : "=f"(r) : "f"(x)); return r; }

// ---------------------------------------------------------------------------
// Kernel 1: per-cell class-presence bitmask (stride-2 NN downsample).
// One warp per 2 cells; 8 independent int4 loads per thread (MLP=8).
// ---------------------------------------------------------------------------
__global__ void __launch_bounds__(256) k_presence(const int4* __restrict__ t4) {
    int gwarp = (blockIdx.x * blockDim.x + threadIdx.x) >> 5;  // 0..8191
    int lane  = threadIdx.x & 31;
    int cellA = gwarp << 1;
    int bA    = cellA >> 10;
    int restA = cellA & 1023;
    int chA   = restA >> 5;
    int cwA   = restA & 31;

    int baseA = (bA << 18) + (chA << 13) + (cwA << 3);
    int baseB = baseA + 8;

    int4 qa[4], qb[4];
#pragma unroll
    for (int k = 0; k < 4; ++k) {
        int e = lane + (k << 5);
        int i = e >> 3, jj = e & 7;
        int roff = (i << 9) + jj;
        qa[k] = __ldg(&t4[baseA + roff]);
        qb[k] = __ldg(&t4[baseB + roff]);
    }
    unsigned mA = 0, mB = 0;
#pragma unroll
    for (int k = 0; k < 4; ++k) {
        mA |= (1u << (qa[k].x & 31)) | (1u << (qa[k].z & 31));
        mB |= (1u << (qb[k].x & 31)) | (1u << (qb[k].z & 31));
    }
    mA = __reduce_or_sync(0xFFFFFFFFu, mA);
    mB = __reduce_or_sync(0xFFFFFFFFu, mB);
    if (lane == 0) { g_masks[cellA] = mA; g_masks[cellA + 1] = mB; }
}

// ---------------------------------------------------------------------------
// BCE element (R4 form): al += lg2(1+e^{-|x|}); aa += relu(se ? -x : x)
// ---------------------------------------------------------------------------
__device__ __forceinline__ void bce_acc(float x, unsigned sgn, float& al, float& aa) {
    float t = ex2_(fabsf(x) * -1.4426950408889634f);   // e^{-|x|} in (0,1]
    al += lg2_(1.0f + t);                              // log2(1+t)
    float y = __int_as_float(__float_as_int(x) ^ sgn); // se ? -x : x
    aa += fmaxf(y, 0.0f);
}

// ---------------------------------------------------------------------------
// Kernel 2: streaming loss reduction (R4 verbatim).
// ---------------------------------------------------------------------------
__global__ void __launch_bounds__(LOSS_THREADS) k_loss(const float4* __restrict__ p4) {
    int tid = blockIdx.x * blockDim.x + threadIdx.x;
    int lin = tid << 2;
    int w   = lin & 511;
    int h   = (lin >> 9) & 511;
    int cellhw = ((h >> 4) << 5) + (w >> 4);   // loop-invariant
    int bc0 = lin >> 18;                       // b*19+c at iter 0; +8 per iter

    float al0 = 0.f, al1 = 0.f, aa0 = 0.f, aa1 = 0.f;
#pragma unroll 2
    for (int k = 0; k < LOSS_ITERS; ++k) {
        float4 v = __ldcs(p4 + tid + k * LOSS_STRIDE);
        int bc = bc0 + (k << 3);
        int b  = bc / 19;
        int c  = bc - b * 19;
        unsigned mask = g_masks[(b << 10) + cellhw];
        unsigned sgn  = ((mask >> c) & 1u) << 31;
        bce_acc(v.x, sgn, al0, aa0);
        bce_acc(v.y, sgn, al1, aa1);
        bce_acc(v.z, sgn, al0, aa0);
        bce_acc(v.w, sgn, al1, aa1);
    }
    // single fp64 conversion per thread
    double acc = (double)(al0 + al1) * 0.6931471805599453 + (double)(aa0 + aa1);

    // deterministic block reduction
    __shared__ double smem[LOSS_THREADS / 32];
    for (int o = 16; o > 0; o >>= 1) acc += __shfl_down_sync(0xFFFFFFFFu, acc, o);
    if ((threadIdx.x & 31) == 0) smem[threadIdx.x >> 5] = acc;
    __syncthreads();
    if (threadIdx.x < (LOSS_THREADS / 32)) {
        double a = smem[threadIdx.x];
        for (int o = (LOSS_THREADS / 64); o > 0; o >>= 1)
            a += __shfl_down_sync(0xFFu, a, o);
        if (threadIdx.x == 0) g_partial[blockIdx.x] = a;
    }
}

// ---------------------------------------------------------------------------
// Kernel 3: final deterministic reduction -> mean (R4 verbatim).
// ---------------------------------------------------------------------------
__global__ void __launch_bounds__(256) k_final(float* __restrict__ out) {
    __shared__ double smem[8];
    double a = 0.0;
    for (int i = threadIdx.x; i < LOSS_BLOCKS; i += 256) a += g_partial[i];
    for (int o = 16; o > 0; o >>= 1) a += __shfl_down_sync(0xFFFFFFFFu, a, o);
    if ((threadIdx.x & 31) == 0) smem[threadIdx.x >> 5] = a;
    __syncthreads();
    if (threadIdx.x < 8) {
        double v = smem[threadIdx.x];
        for (int o = 4; o > 0; o >>= 1) v += __shfl_down_sync(0xFFu, v, o);
        if (threadIdx.x == 0) out[0] = (float)(v * (1.0 / (double)N_ELEMS));
    }
}

extern "C" void kernel_launch(void* const* d_in, const int* in_sizes, int n_in,
                              void* d_out, int out_size) {
    const float*  preds   = (const float*)d_in[0];
    const int4*   targets = (const int4*)d_in[1];
    float*        out     = (float*)d_out;

    k_presence<<<1024, 256>>>(targets);
    k_loss<<<LOSS_BLOCKS, LOSS_THREADS>>>((const float4*)preds);
    k_final<<<1, 256>>>(out);
}